// round 7
// baseline (speedup 1.0000x reference)
#include <cuda_runtime.h>
#include <cuda_fp16.h>
#include <cstdint>

#define B_   32768
#define D_   1472
#define E_   8
#define H1_  512
#define H2_  256
#define T_   2
#define NSLAB 256          // one stats slab per 128-row m-block

// ---------------- scratch (static device arrays; no cudaMalloc) ------------
__device__ float g_h1[(size_t)E_ * B_ * H1_];
__device__ float g_h2[(size_t)E_ * B_ * H2_];
__device__ float g_gates[(size_t)T_ * B_ * E_];
__device__ float g_psum[(size_t)E_ * H1_ * NSLAB];
__device__ float g_psq [(size_t)E_ * H1_ * NSLAB];
__device__ float g_s1[E_ * H1_], g_t1[E_ * H1_];
__device__ float g_s2[E_ * H2_], g_t2[E_ * H2_];
// fp16 pre-splits: x -> hi+lo pair; weights -> hi only
__device__ __half g_xh[(size_t)B_ * D_];
__device__ __half g_xl[(size_t)B_ * D_];
__device__ __half g_w1h[(size_t)E_ * D_ * H1_];
__device__ __half g_w2h[(size_t)E_ * H1_ * H2_];

// ---------------- PTX helpers ----------------------------------------------
__device__ __forceinline__ uint32_t s2u(const void* p) {
    return (uint32_t)__cvta_generic_to_shared(p);
}
__device__ __forceinline__ void ldsm_x4(uint32_t* r, uint32_t a) {
    asm volatile("ldmatrix.sync.aligned.m8n8.x4.shared.b16 {%0,%1,%2,%3}, [%4];"
        : "=r"(r[0]), "=r"(r[1]), "=r"(r[2]), "=r"(r[3]) : "r"(a));
}
__device__ __forceinline__ void ldsm_x4t(uint32_t* r, uint32_t a) {
    asm volatile("ldmatrix.sync.aligned.m8n8.x4.trans.shared.b16 {%0,%1,%2,%3}, [%4];"
        : "=r"(r[0]), "=r"(r[1]), "=r"(r[2]), "=r"(r[3]) : "r"(a));
}
__device__ __forceinline__ void mma16816(float* d, const uint32_t* a, const uint32_t* b) {
    asm volatile("mma.sync.aligned.m16n8k16.row.col.f32.f16.f16.f32 "
        "{%0,%1,%2,%3}, {%4,%5,%6,%7}, {%8,%9}, {%0,%1,%2,%3};"
        : "+f"(d[0]), "+f"(d[1]), "+f"(d[2]), "+f"(d[3])
        : "r"(a[0]), "r"(a[1]), "r"(a[2]), "r"(a[3]), "r"(b[0]), "r"(b[1]));
}
__device__ __forceinline__ void cp16(uint32_t dst, const void* src) {
    asm volatile("cp.async.cg.shared.global [%0], [%1], 16;"
        :: "r"(dst), "l"(src) : "memory");
}
__device__ __forceinline__ void cp_commit() {
    asm volatile("cp.async.commit_group;" ::: "memory");
}
__device__ __forceinline__ void cp_wait0() {
    asm volatile("cp.async.wait_group 0;" ::: "memory");
}
__device__ __forceinline__ void cp_wait1() {
    asm volatile("cp.async.wait_group 1;" ::: "memory");
}

// fp32 -> fp16 hi + fp16 residual lo, packed pairs
__device__ __forceinline__ void split_pair_h(float x, float y,
                                             uint32_t& hi, uint32_t& lo) {
    __half hx = __float2half_rn(x);
    __half hy = __float2half_rn(y);
    __half lx = __float2half_rn(x - __half2float(hx));
    __half ly = __float2half_rn(y - __half2float(hy));
    __half2 h = __halves2half2(hx, hy);
    __half2 l = __halves2half2(lx, ly);
    hi = *reinterpret_cast<uint32_t*>(&h);
    lo = *reinterpret_cast<uint32_t*>(&l);
}

// ---------------- SMEM layout (bytes), 3 stages ------------------------------
#define ASTR 40
#define BSTR 136
#define STG_SZ 29184
#define AH_(b) ((b) * STG_SZ)
#define AL_(b) ((b) * STG_SZ + 10240)
#define BH_(b) ((b) * STG_SZ + 20480)
#define SMEM_BYTES (3 * STG_SZ)   // 87552 -> 2 CTAs/SM (175 KB)

// ---------------------------------------------------------------------------
// fp16 2-product HMMA GEMM: D = (ah+al)*bh, 3-stage cp.async pipeline,
// one __syncthreads per ktile, 2 CTAs/SM, warp tile m32 x n64,
// fused deterministic BN batch stats in the epilogue.
// ---------------------------------------------------------------------------
template<int K_TOT, int N_TOT, int ASRC, int NB>
__global__ __launch_bounds__(256, 2) void gemm_hmma(
    const float* __restrict__ bias_all)
{
    extern __shared__ char smem[];
    __shared__ float sred_s[4][128];
    __shared__ float sred_q[4][128];
    const uint32_t sb = s2u(smem);
    const int tid  = threadIdx.x;
    const int lane = tid & 31;
    const int wid  = tid >> 5;
    const int wm   = (wid & 3) * 32;   // 4 warp rows of 32
    const int wn   = (wid >> 2) * 64;  // 2 warp cols of 64

    const int e  = blockIdx.x / NB;
    const int bn = (blockIdx.x % NB) * 128;
    const int bm = blockIdx.y * 128;

    const __half* Ah = g_xh + (size_t)bm * K_TOT;                   // ASRC==0
    const __half* Al = g_xl + (size_t)bm * K_TOT;
    const float* Af = g_h1 + ((size_t)e * B_ + bm) * (size_t)K_TOT; // ASRC==1
    const __half* Wh =
        ((ASRC == 0) ? g_w1h : g_w2h) + (size_t)e * K_TOT * N_TOT + bn;
    const float* S  = g_s1 + e * K_TOT;
    const float* Tt = g_t1 + e * K_TOT;

    float acc[2][8][4];
    #pragma unroll
    for (int i = 0; i < 2; ++i)
        #pragma unroll
        for (int j = 0; j < 8; ++j)
            #pragma unroll
            for (int r = 0; r < 4; ++r) acc[i][j][r] = 0.f;

    constexpr int NT = K_TOT / 32;
    float4 av[4];   // ASRC==1 register staging (holds chunk kt+1 during iter kt)

    // ============ prologue: stage 0 and stage 1 in flight ============
    // helper lambdas expressed as macros over locals
    #define CP_A_STAGE(stg, k0)                                              \
        do {                                                                 \
            _Pragma("unroll")                                                \
            for (int i = 0; i < 4; ++i) {                                    \
                int c = tid + i * 256, cc = c & 511;                         \
                int row = cc >> 2, k4 = cc & 3;                              \
                const __half* src = ((c < 512) ? Ah : Al)                    \
                                    + (size_t)row * K_TOT + (k0) + k4 * 8;   \
                cp16(sb + ((c < 512) ? AH_(stg) : AL_(stg))                  \
                        + row * 80 + k4 * 16, src);                          \
            }                                                                \
        } while (0)
    #define CP_B_STAGE(stg, k0)                                              \
        do {                                                                 \
            _Pragma("unroll")                                                \
            for (int i = 0; i < 2; ++i) {                                    \
                int cc = tid + i * 256;                                      \
                int kr = cc >> 4, n16 = cc & 15;                             \
                cp16(sb + BH_(stg) + kr * 272 + n16 * 16,                    \
                     Wh + (size_t)((k0) + kr) * N_TOT + n16 * 8);            \
            }                                                                \
        } while (0)
    #define LDG_AV(k0)                                                       \
        do {                                                                 \
            _Pragma("unroll")                                                \
            for (int i = 0; i < 4; ++i) {                                    \
                int idx = tid + i * 256;                                     \
                av[i] = *(const float4*)(Af + (size_t)(idx >> 3) * K_TOT     \
                                            + (k0) + (idx & 7) * 4);         \
            }                                                                \
        } while (0)
    #define STS_AV(stg, k0)                                                  \
        do {                                                                 \
            __half* aH = (__half*)(smem + AH_(stg));                         \
            __half* aL = (__half*)(smem + AL_(stg));                         \
            _Pragma("unroll")                                                \
            for (int i = 0; i < 4; ++i) {                                    \
                int idx = tid + i * 256;                                     \
                int row = idx >> 3, c4 = (idx & 7) * 4;                      \
                float4 v = av[i];                                            \
                int kc = (k0) + c4;                                          \
                float4 s4 = *(const float4*)(S + kc);                        \
                float4 t4 = *(const float4*)(Tt + kc);                       \
                v.x = fmaxf(0.f, fmaf(v.x, s4.x, t4.x));                     \
                v.y = fmaxf(0.f, fmaf(v.y, s4.y, t4.y));                     \
                v.z = fmaxf(0.f, fmaf(v.z, s4.z, t4.z));                     \
                v.w = fmaxf(0.f, fmaf(v.w, s4.w, t4.w));                     \
                uint32_t h0, l0, h1, l1;                                     \
                split_pair_h(v.x, v.y, h0, l0);                              \
                split_pair_h(v.z, v.w, h1, l1);                              \
                int off = row * ASTR + c4;                                   \
                *(uint32_t*)&aH[off]     = h0;                               \
                *(uint32_t*)&aH[off + 2] = h1;                               \
                *(uint32_t*)&aL[off]     = l0;                               \
                *(uint32_t*)&aL[off + 2] = l1;                               \
            }                                                                \
        } while (0)

    if (ASRC == 0) {
        CP_A_STAGE(0, 0);
        CP_B_STAGE(0, 0);
        cp_commit();
        CP_A_STAGE(1, 32);
        CP_B_STAGE(1, 32);
        cp_commit();
    } else {
        LDG_AV(0);
        STS_AV(0, 0);
        LDG_AV(32);            // chunk 1 held in regs; STS'd in iter 0
        CP_B_STAGE(0, 0);
        cp_commit();
        CP_B_STAGE(1, 32);
        cp_commit();
    }

    // ============ main loop: one barrier per ktile ============
    for (int kt = 0; kt < NT; ++kt) {
        const int cur = kt % 3;

        if (kt + 1 < NT) cp_wait1();   // stage kt complete, kt+1 in flight
        else             cp_wait0();   // final stage must be fully drained
        __syncthreads();               // stage kt visible; prior reads done

        // ---- issue stage kt+2 (A via regs for ASRC==1: STS kt+1, LDG kt+2)
        if (ASRC == 1 && kt + 1 < NT) {
            STS_AV((kt + 1) % 3, (kt + 1) * 32);   // buffer free since iter kt-2
            if (kt + 2 < NT) LDG_AV((kt + 2) * 32);
        }
        if (kt + 2 < NT) {
            const int stg = (kt + 2) % 3;
            if (ASRC == 0) CP_A_STAGE(stg, (kt + 2) * 32);
            CP_B_STAGE(stg, (kt + 2) * 32);
        }
        cp_commit();   // always commit (possibly empty) to keep group counts aligned

        // ---- MMAs on stage cur
        const __half* aH = (const __half*)(smem + AH_(cur));
        const __half* aL = (const __half*)(smem + AL_(cur));
        const __half* bH = (const __half*)(smem + BH_(cur));
        #pragma unroll
        for (int ks = 0; ks < 2; ++ks) {
            const int k0s = ks * 16;
            uint32_t bh[4][4];
            #pragma unroll
            for (int g = 0; g < 4; ++g) {
                int r = k0s + (lane & 15);
                int c = wn + g * 16 + (lane >> 4) * 8;
                ldsm_x4t(bh[g], s2u(&bH[r * BSTR + c]));
            }
            #pragma unroll
            for (int mi = 0; mi < 2; ++mi) {
                uint32_t ah[4], al[4];
                int r = wm + mi * 16 + (lane & 15);
                int c = k0s + (lane >> 4) * 8;
                ldsm_x4(ah, s2u(&aH[r * ASTR + c]));
                ldsm_x4(al, s2u(&aL[r * ASTR + c]));
                #pragma unroll
                for (int ni = 0; ni < 8; ++ni) {
                    const uint32_t* pb = &bh[ni >> 1][(ni & 1) * 2];
                    mma16816(acc[mi][ni], ah, pb);
                    mma16816(acc[mi][ni], al, pb);
                }
            }
        }
    }
    __syncthreads();

    // ---- epilogue: +bias, store, fused BN stats (deterministic)
    float* C = ((ASRC == 0) ? g_h1 : g_h2) + ((size_t)e * B_ + bm) * N_TOT + bn;
    const float* bias = bias_all + e * N_TOT + bn;
    #pragma unroll
    for (int ni = 0; ni < 8; ++ni) {
        int c0 = wn + ni * 8 + (lane & 3) * 2;
        float b0 = bias[c0], b1 = bias[c0 + 1];
        float ss0 = 0.f, ss1 = 0.f, qq0 = 0.f, qq1 = 0.f;
        #pragma unroll
        for (int mi = 0; mi < 2; ++mi) {
            int r0 = wm + mi * 16 + (lane >> 2);
            float v00 = acc[mi][ni][0] + b0, v01 = acc[mi][ni][1] + b1;
            float v10 = acc[mi][ni][2] + b0, v11 = acc[mi][ni][3] + b1;
            float2 w0 = { v00, v01 }, w1 = { v10, v11 };
            *(float2*)(C + (size_t)r0 * N_TOT + c0) = w0;
            *(float2*)(C + (size_t)(r0 + 8) * N_TOT + c0) = w1;
            ss0 += v00 + v10;  ss1 += v01 + v11;
            qq0 += v00 * v00 + v10 * v10;
            qq1 += v01 * v01 + v11 * v11;
        }
        #pragma unroll
        for (int o = 4; o < 32; o <<= 1) {
            ss0 += __shfl_xor_sync(0xffffffffu, ss0, o);
            ss1 += __shfl_xor_sync(0xffffffffu, ss1, o);
            qq0 += __shfl_xor_sync(0xffffffffu, qq0, o);
            qq1 += __shfl_xor_sync(0xffffffffu, qq1, o);
        }
        if (lane < 4) {
            int c = wn + ni * 8 + lane * 2;
            int rg = wid & 3;
            sred_s[rg][c] = ss0; sred_s[rg][c + 1] = ss1;
            sred_q[rg][c] = qq0; sred_q[rg][c + 1] = qq1;
        }
    }
    __syncthreads();
    if (tid < 128) {
        float s = sred_s[0][tid] + sred_s[1][tid] + sred_s[2][tid] + sred_s[3][tid];
        float q = sred_q[0][tid] + sred_q[1][tid] + sred_q[2][tid] + sred_q[3][tid];
        size_t idx = ((size_t)e * N_TOT + bn + tid) * NSLAB + blockIdx.y;
        g_psum[idx] = s;
        g_psq[idx]  = q;
    }
}

// ---------------------------------------------------------------------------
// fp32 -> fp16 hi/lo split (x) and fp32 -> fp16 round (weights)
// ---------------------------------------------------------------------------
__global__ __launch_bounds__(256) void split_f16(
    const float* __restrict__ src, __half* __restrict__ dh,
    __half* __restrict__ dl, size_t n8)
{
    size_t i = (size_t)blockIdx.x * 256 + threadIdx.x;
    if (i >= n8) return;
    const float4* s = (const float4*)src + i * 2;
    float4 v0 = s[0], v1 = s[1];
    uint4 h, l;
    split_pair_h(v0.x, v0.y, h.x, l.x);
    split_pair_h(v0.z, v0.w, h.y, l.y);
    split_pair_h(v1.x, v1.y, h.z, l.z);
    split_pair_h(v1.z, v1.w, h.w, l.w);
    ((uint4*)dh)[i] = h;
    ((uint4*)dl)[i] = l;
}

__global__ __launch_bounds__(256) void round_f16(
    const float* __restrict__ src, __half* __restrict__ dh, size_t n8)
{
    size_t i = (size_t)blockIdx.x * 256 + threadIdx.x;
    if (i >= n8) return;
    const float4* s = (const float4*)src + i * 2;
    float4 v0 = s[0], v1 = s[1];
    __half2 h0 = __floats2half2_rn(v0.x, v0.y);
    __half2 h1 = __floats2half2_rn(v0.z, v0.w);
    __half2 h2 = __floats2half2_rn(v1.x, v1.y);
    __half2 h3 = __floats2half2_rn(v1.z, v1.w);
    uint4 h = { *(uint32_t*)&h0, *(uint32_t*)&h1, *(uint32_t*)&h2, *(uint32_t*)&h3 };
    ((uint4*)dh)[i] = h;
}

// ---------------------------------------------------------------------------
// Gates (Round-5 variant, measured 140us): 4 rows per warp, scalar X loads.
// ---------------------------------------------------------------------------
__global__ __launch_bounds__(256) void gates_kernel(
    const float* __restrict__ X, const float* __restrict__ Wg,
    const float* __restrict__ bg)
{
    int warp = (blockIdx.x * blockDim.x + threadIdx.x) >> 5;
    int lane = threadIdx.x & 31;
    int r0 = warp * 4;
    if (r0 >= B_) return;
    const float* x0 = X + (size_t)(r0 + 0) * D_;
    const float* x1 = X + (size_t)(r0 + 1) * D_;
    const float* x2 = X + (size_t)(r0 + 2) * D_;
    const float* x3 = X + (size_t)(r0 + 3) * D_;

    float acc[4][16];
    #pragma unroll
    for (int r = 0; r < 4; ++r)
        #pragma unroll
        for (int i = 0; i < 16; ++i) acc[r][i] = 0.f;

    for (int d = lane; d < D_; d += 32) {
        float xv0 = x0[d], xv1 = x1[d], xv2 = x2[d], xv3 = x3[d];
        #pragma unroll
        for (int t = 0; t < T_; ++t) {
            const float* wr = Wg + ((size_t)t * D_ + d) * E_;
            float4 w0 = *(const float4*)wr;
            float4 w1 = *(const float4*)(wr + 4);
            float wv[8] = { w0.x, w0.y, w0.z, w0.w, w1.x, w1.y, w1.z, w1.w };
            #pragma unroll
            for (int ee = 0; ee < 8; ++ee) {
                acc[0][t*8+ee] = fmaf(xv0, wv[ee], acc[0][t*8+ee]);
                acc[1][t*8+ee] = fmaf(xv1, wv[ee], acc[1][t*8+ee]);
                acc[2][t*8+ee] = fmaf(xv2, wv[ee], acc[2][t*8+ee]);
                acc[3][t*8+ee] = fmaf(xv3, wv[ee], acc[3][t*8+ee]);
            }
        }
    }
    #pragma unroll
    for (int r = 0; r < 4; ++r)
        #pragma unroll
        for (int i = 0; i < 16; ++i)
            #pragma unroll
            for (int o = 16; o > 0; o >>= 1)
                acc[r][i] += __shfl_xor_sync(0xffffffffu, acc[r][i], o);

    if (lane < 4) {
        #pragma unroll
        for (int r = 0; r < 4; ++r) {
            if (lane == r) {
                #pragma unroll
                for (int t = 0; t < T_; ++t) {
                    float v[8], m = -1e30f;
                    #pragma unroll
                    for (int e = 0; e < 8; ++e) {
                        v[e] = acc[r][t*8+e] + bg[t*8+e];
                        m = fmaxf(m, v[e]);
                    }
                    float s = 0.f;
                    #pragma unroll
                    for (int e = 0; e < 8; ++e) { v[e] = expf(v[e] - m); s += v[e]; }
                    float inv = 1.f / s;
                    #pragma unroll
                    for (int e = 0; e < 8; ++e)
                        g_gates[((size_t)t * B_ + r0 + r) * E_ + e] = v[e] * inv;
                }
            }
        }
    }
}

// ---------------------------------------------------------------------------
// Combine per-mblock stats -> BN scale/shift (deterministic, 256 slabs)
// ---------------------------------------------------------------------------
__global__ __launch_bounds__(256) void stats_combine(
    int which, int Hc, const float* __restrict__ gamma,
    const float* __restrict__ beta)
{
    int i = blockIdx.x * 256 + threadIdx.x;
    if (i >= E_ * Hc) return;
    const float* ps = g_psum + (size_t)i * NSLAB;
    const float* pq = g_psq  + (size_t)i * NSLAB;
    float s = 0.f, q = 0.f;
    for (int j = 0; j < NSLAB; ++j) { s += ps[j]; q += pq[j]; }
    const float invB = 1.f / (float)B_;
    float mu  = s * invB;
    float var = q * invB - mu * mu;
    float inv = rsqrtf(var + 1e-5f);
    float gg = gamma[i], bb = beta[i];
    float* Sd = (which == 0) ? g_s1 : g_s2;
    float* Td = (which == 0) ? g_t1 : g_t2;
    Sd[i] = gg * inv;
    Td[i] = bb - gg * mu * inv;
}

// ---------------------------------------------------------------------------
// Final: out[t,b,e*H2+k] = relu(BN2(g_h2[e,b,k])) * gates[t,b,e]
// ---------------------------------------------------------------------------
__global__ __launch_bounds__(256) void final_kernel(float* __restrict__ out)
{
    size_t idx = (size_t)blockIdx.x * blockDim.x + threadIdx.x;
    int k4 = (int)(idx & 63);
    int b  = (int)((idx >> 6) & (B_ - 1));
    int e  = (int)(idx >> 21);
    int k  = k4 * 4;

    float4 h  = *(const float4*)(g_h2 + (((size_t)e * B_ + b) * H2_ + k));
    float4 s  = *(const float4*)(g_s2 + e * H2_ + k);
    float4 tt = *(const float4*)(g_t2 + e * H2_ + k);
    float4 y;
    y.x = fmaxf(0.f, fmaf(h.x, s.x, tt.x));
    y.y = fmaxf(0.f, fmaf(h.y, s.y, tt.y));
    y.z = fmaxf(0.f, fmaf(h.z, s.z, tt.z));
    y.w = fmaxf(0.f, fmaf(h.w, s.w, tt.w));

    float ga = g_gates[(size_t)b * E_ + e];
    float gb = g_gates[(size_t)B_ * E_ + (size_t)b * E_ + e];

    size_t o0 = (size_t)b * (E_ * H2_) + e * H2_ + k;
    size_t o1 = (size_t)B_ * (E_ * H2_) + o0;
    float4 v0 = { y.x * ga, y.y * ga, y.z * ga, y.w * ga };
    float4 v1 = { y.x * gb, y.y * gb, y.z * gb, y.w * gb };
    *(float4*)(out + o0) = v0;
    *(float4*)(out + o1) = v1;
}

// ---------------------------------------------------------------------------
extern "C" void kernel_launch(void* const* d_in, const int* in_sizes, int n_in,
                              void* d_out, int out_size)
{
    const float* x   = (const float*)d_in[0];
    const float* W1  = (const float*)d_in[1];
    const float* b1  = (const float*)d_in[2];
    const float* g1  = (const float*)d_in[3];
    const float* be1 = (const float*)d_in[4];
    const float* W2  = (const float*)d_in[5];
    const float* b2  = (const float*)d_in[6];
    const float* g2  = (const float*)d_in[7];
    const float* be2 = (const float*)d_in[8];
    const float* Wg  = (const float*)d_in[9];
    const float* bg  = (const float*)d_in[10];
    float* out = (float*)d_out;

    cudaFuncSetAttribute(gemm_hmma<D_, H1_, 0, 4>,
        cudaFuncAttributeMaxDynamicSharedMemorySize, SMEM_BYTES);
    cudaFuncSetAttribute(gemm_hmma<H1_, H2_, 1, 2>,
        cudaFuncAttributeMaxDynamicSharedMemorySize, SMEM_BYTES);

    // ---- pre-splits / rounds
    {
        __half *xh, *xl, *w1h, *w2h;
        cudaGetSymbolAddress((void**)&xh,  g_xh);
        cudaGetSymbolAddress((void**)&xl,  g_xl);
        cudaGetSymbolAddress((void**)&w1h, g_w1h);
        cudaGetSymbolAddress((void**)&w2h, g_w2h);
        size_t nx = (size_t)B_ * D_ / 8;
        size_t n1 = (size_t)E_ * D_ * H1_ / 8;
        size_t n2 = (size_t)E_ * H1_ * H2_ / 8;
        split_f16<<<(unsigned)((nx + 255) / 256), 256>>>(x, xh, xl, nx);
        round_f16<<<(unsigned)((n1 + 255) / 256), 256>>>(W1, w1h, n1);
        round_f16<<<(unsigned)((n2 + 255) / 256), 256>>>(W2, w2h, n2);
    }

    gates_kernel<<<B_ / 32, 256>>>(x, Wg, bg);

    gemm_hmma<D_, H1_, 0, 4>
        <<<dim3(4 * E_, B_ / 128), 256, SMEM_BYTES>>>(b1);
    stats_combine<<<(E_ * H1_ + 255) / 256, 256>>>(0, H1_, g1, be1);

    gemm_hmma<H1_, H2_, 1, 2>
        <<<dim3(2 * E_, B_ / 128), 256, SMEM_BYTES>>>(b2);
    stats_combine<<<(E_ * H2_ + 255) / 256, 256>>>(1, H2_, g2, be2);

    final_kernel<<<(unsigned)((size_t)E_ * B_ * (H2_ / 4) / 256), 256>>>(out);
}